// round 12
// baseline (speedup 1.0000x reference)
#include <cuda_runtime.h>
#include <cuda_fp16.h>
#include <cstdint>
#include <math.h>

// ---------------- problem constants ----------------
#define DD 768
#define RR 16
#define TT 8
#define M_ROWS 8192
#define NOUT 2304
#define KM2 192          // padded low-rank K per branch (144 real + 48 zero)

// ---------------- static scratch ----------------
__device__ __align__(16) __half g_xt[M_ROWS * DD];    // x in fp16
__device__ __align__(16) __half g_wt[NOUT * DD];      // W (+ folded dW) in fp16
__device__ __align__(16) __half g_Bqs[DD * KM2];      // scaled B_q  [e][j]
__device__ __align__(16) __half g_Bvs[DD * KM2];
__device__ __align__(16) __half g_AqT[DD * KM2];      // A_q^T       [d][j]
__device__ __align__(16) __half g_AvT[DD * KM2];
__device__ float g_normsq[32];                        // [Aq(8),Bq(8),Av(8),Bv(8)]

// ---------------- helpers ----------------
__device__ __forceinline__ void cp16(void* sdst, const void* gsrc) {
    unsigned s = (unsigned)__cvta_generic_to_shared(sdst);
    asm volatile("cp.async.cg.shared.global [%0], [%1], 16;\n" :: "r"(s), "l"(gsrc));
}

__device__ __forceinline__ void ldm_x4(uint32_t& d0, uint32_t& d1, uint32_t& d2,
                                       uint32_t& d3, uint32_t saddr) {
    asm volatile("ldmatrix.sync.aligned.m8n8.x4.shared.b16 {%0,%1,%2,%3}, [%4];"
                 : "=r"(d0), "=r"(d1), "=r"(d2), "=r"(d3) : "r"(saddr));
}

__device__ __forceinline__ void mma_fp16(float c[4], const uint32_t a[4], const uint32_t b[2]) {
    asm volatile(
        "mma.sync.aligned.m16n8k16.row.col.f32.f16.f16.f32 "
        "{%0,%1,%2,%3},{%4,%5,%6,%7},{%8,%9},{%0,%1,%2,%3};\n"
        : "+f"(c[0]), "+f"(c[1]), "+f"(c[2]), "+f"(c[3])
        : "r"(a[0]), "r"(a[1]), "r"(a[2]), "r"(a[3]),
          "r"(b[0]), "r"(b[1]));
}

// ---------------- fused prepass: x-convert | w-convert | norms ----------------
__device__ __forceinline__ void convert_seg(const float4* __restrict__ src,
                                            uint4* __restrict__ dst,
                                            int bid_local, int nb) {
    const int stride = nb * 256;
    int i = bid_local * 256 + threadIdx.x;
#pragma unroll
    for (int u = 0; u < 4; u++) {
        int k = i + u * stride;
        float4 a = src[2 * k], b = src[2 * k + 1];
        __half2 h0 = __floats2half2_rn(a.x, a.y);
        __half2 h1 = __floats2half2_rn(a.z, a.w);
        __half2 h2 = __floats2half2_rn(b.x, b.y);
        __half2 h3 = __floats2half2_rn(b.z, b.w);
        uint4 o;
        o.x = *reinterpret_cast<uint32_t*>(&h0);
        o.y = *reinterpret_cast<uint32_t*>(&h1);
        o.z = *reinterpret_cast<uint32_t*>(&h2);
        o.w = *reinterpret_cast<uint32_t*>(&h3);
        dst[k] = o;
    }
}

__global__ void prep_kernel(const float4* __restrict__ x, const float4* __restrict__ wmid,
                            const float* __restrict__ Aq, const float* __restrict__ Bq,
                            const float* __restrict__ Av, const float* __restrict__ Bv) {
    int bid = blockIdx.x;
    if (bid < 768) {
        convert_seg(x, (uint4*)g_xt, bid, 768);
    } else if (bid < 840) {
        convert_seg(wmid, (uint4*)(g_wt + (size_t)DD * DD), bid - 768, 72);
    } else {
        __shared__ float red[256];
        int b = bid - 840, which = b >> 3, t = b & 7;
        const float* p = (which == 0) ? Aq : (which == 1) ? Bq : (which == 2) ? Av : Bv;
        p += t * (RR * DD);
        float s = 0.f;
        for (int i = threadIdx.x; i < RR * DD; i += 256) { float v = p[i]; s += v * v; }
        red[threadIdx.x] = s;
        __syncthreads();
        for (int o = 128; o > 0; o >>= 1) {
            if (threadIdx.x < o) red[threadIdx.x] += red[threadIdx.x + o];
            __syncthreads();
        }
        if (threadIdx.x == 0) g_normsq[b] = red[0];
    }
}

// Builds (fp16): Bqs/Bvs [768][192] with beta/norm (or alpha) folded in,
// and AqT/AvT [768][192] = transposed A stacks. Cols 144-191 zero.
__global__ void build_kernel(const float* __restrict__ Aq, const float* __restrict__ laq,
                             const float* __restrict__ Av, const float* __restrict__ lav,
                             const float* __restrict__ Bq, const float* __restrict__ lbq,
                             const float* __restrict__ Bv, const float* __restrict__ lbv,
                             const float* __restrict__ gate, const float* __restrict__ alpha) {
    float sq[TT], sv[TT];
    {
        float mx = gate[0];
        for (int t = 1; t < TT; t++) mx = fmaxf(mx, gate[t]);
        float e[TT], se = 0.f;
        for (int t = 0; t < TT; t++) { e[t] = expf(gate[t] - mx); se += e[t]; }
        for (int t = 0; t < TT; t++) {
            float beta = e[t] / se;
            sq[t] = beta / (sqrtf(g_normsq[t]) * sqrtf(g_normsq[8 + t]));
            sv[t] = beta / (sqrtf(g_normsq[16 + t]) * sqrtf(g_normsq[24 + t]));
        }
    }
    float acur = alpha[TT];
    int i0 = blockIdx.x * blockDim.x + threadIdx.x;
    int stride = gridDim.x * blockDim.x;
    for (int i = i0; i < DD * KM2; i += stride) {
        int d = i / KM2, j = i % KM2;
        float bq = 0.f, bv = 0.f, aq = 0.f, av = 0.f;
        if (j < 128) {
            int t = j >> 4, r = j & 15;
            bq = Bq[t * (DD * RR) + d * RR + r] * sq[t];
            bv = Bv[t * (DD * RR) + d * RR + r] * sv[t];
            aq = Aq[j * DD + d];
            av = Av[j * DD + d];
        } else if (j < 144) {
            bq = lbq[d * RR + (j - 128)] * acur;
            bv = lbv[d * RR + (j - 128)] * acur;
            aq = laq[(j - 128) * DD + d];
            av = lav[(j - 128) * DD + d];
        }
        g_Bqs[i] = __float2half_rn(bq);
        g_Bvs[i] = __float2half_rn(bv);
        g_AqT[i] = __float2half_rn(aq);
        g_AvT[i] = __float2half_rn(av);
    }
}

// ---------------- fp16 mma.sync GEMM machinery ----------------
// Block 128x192, 12 warps in 2x6 grid, warp tile 64x32.
// 384 thr/CTA -> reg cap 170: room for double-buffered fragments (ks-pipelined).
#define NS 3
#define BM 128
#define BN 192
#define BK 64
#define NTHR 384
#define LDSH 72   // padded row (144 B): 16B-step row offsets -> conflict-free ldmatrix
#define NCHUNK ((BM + BN) * 8)   // 2560 16B-chunks per stage

// MODE 0 (delta): W'[e,d] = fp16( qkv_w[e_glob,d] + sum_j Bs[e,j]*AT[d,j] ), KT=3
//   grid (4,6,2): z=0 -> q branch (e_glob=e), z=1 -> v branch (e_glob=1536+e)
// MODE 1 (main): out[8192,2304] = xt @ wt^T + bias, KT=12, grid (12,64)
template <int MODE>
__global__ __launch_bounds__(NTHR, 1) void gemm_fp16(const float* __restrict__ wsrc,
                                                     float* __restrict__ Cout) {
    extern __shared__ __half sm[];
    __half* As = sm;                        // [NS][BM][LDSH]
    __half* Bs = sm + NS * BM * LDSH;       // [NS][BN][LDSH]

    const int tid = threadIdx.x, lane = tid & 31, w = tid >> 5;
    const int g = lane >> 2, tg = lane & 3;
    const int wm = (w / 6) * 64, wn = (w % 6) * 32;   // 2x6 warp grid, 64x32 tiles
    const int rowbase = blockIdx.y * BM, colbase = blockIdx.x * BN;

    const __half* Ap;
    const __half* Bp;
    int ld, KT;
    if constexpr (MODE == 0) {
        const __half* Asrc = blockIdx.z ? g_Bvs : g_Bqs;
        const __half* Bsrc = blockIdx.z ? g_AvT : g_AqT;
        Ap = Asrc + (size_t)rowbase * KM2;
        Bp = Bsrc + (size_t)colbase * KM2;
        ld = KM2; KT = KM2 / BK;          // 3
    } else {
        Ap = g_xt + (size_t)rowbase * DD;
        Bp = g_wt + (size_t)colbase * DD;
        ld = DD; KT = DD / BK;            // 12
    }

    float acc[4][4][4];
#pragma unroll
    for (int i = 0; i < 4; i++)
#pragma unroll
        for (int j = 0; j < 4; j++)
#pragma unroll
            for (int k = 0; k < 4; k++) acc[i][j][k] = 0.f;

    auto load_tile = [&](int stg, int kt) {
        int kc = kt * BK;
        __half* Ad = As + stg * (BM * LDSH);
        __half* Bd = Bs + stg * (BN * LDSH);
#pragma unroll
        for (int i = 0; i < 7; i++) {          // 7*384 = 2688 >= 2560
            int v = tid + i * NTHR;
            if (v < NCHUNK) {
                if (v < BM * 8) {
                    int r = v >> 3, c = (v & 7) << 3;
                    cp16(Ad + r * LDSH + c, Ap + (size_t)r * ld + kc + c);
                } else {
                    int u = v - BM * 8;
                    int r = u >> 3, c = (u & 7) << 3;
                    cp16(Bd + r * LDSH + c, Bp + (size_t)r * ld + kc + c);
                }
            }
        }
    };

    load_tile(0, 0);
    asm volatile("cp.async.commit_group;\n" ::);
    load_tile(1, 1);
    asm volatile("cp.async.commit_group;\n" ::);

    const uint32_t a_base = (uint32_t)__cvta_generic_to_shared(As);
    const uint32_t b_base = (uint32_t)__cvta_generic_to_shared(Bs);
    const int a_row = wm + (lane & 15);
    const int a_csel = (lane >> 4) << 3;
    const int b_row = wn + (lane & 7) + ((lane >> 4) << 3);
    const int b_csel = ((lane >> 3) & 1) << 3;

    // double-buffered fragments (ks-pipelined)
    uint32_t afr[2][4][4], bfr[2][4][2];

    auto load_frags = [&](int stg, int ks, int buf) {
        const int kk = ks * 16;
#pragma unroll
        for (int fm = 0; fm < 4; fm++) {
            uint32_t addr = a_base +
                (uint32_t)(((stg * BM) + a_row + fm * 16) * LDSH + kk + a_csel) * 2;
            ldm_x4(afr[buf][fm][0], afr[buf][fm][1], afr[buf][fm][2], afr[buf][fm][3], addr);
        }
#pragma unroll
        for (int fn2 = 0; fn2 < 2; fn2++) {
            uint32_t addr = b_base +
                (uint32_t)(((stg * BN) + b_row + fn2 * 16) * LDSH + kk + b_csel) * 2;
            uint32_t r0, r1, r2, r3;
            ldm_x4(r0, r1, r2, r3, addr);
            bfr[buf][fn2 * 2][0] = r0;     bfr[buf][fn2 * 2][1] = r1;
            bfr[buf][fn2 * 2 + 1][0] = r2; bfr[buf][fn2 * 2 + 1][1] = r3;
        }
    };

    for (int kt = 0; kt < KT; kt++) {
        const int stg = kt % NS;
        if (kt == KT - 1) asm volatile("cp.async.wait_group 0;\n" ::);
        else              asm volatile("cp.async.wait_group 1;\n" ::);
        __syncthreads();
        if (kt + 2 < KT) {
            load_tile((kt + 2) % NS, kt + 2);
            asm volatile("cp.async.commit_group;\n" ::);
        }
        load_frags(stg, 0, 0);
#pragma unroll
        for (int ks = 0; ks < 4; ks++) {
            const int cur = ks & 1;
            if (ks < 3) load_frags(stg, ks + 1, cur ^ 1);
#pragma unroll
            for (int fm = 0; fm < 4; fm++)
#pragma unroll
                for (int fn = 0; fn < 4; fn++)
                    mma_fp16(acc[fm][fn], afr[cur][fm], bfr[cur][fn]);
        }
    }

    // epilogue
#pragma unroll
    for (int fm = 0; fm < 4; fm++) {
        int r0 = rowbase + wm + fm * 16 + g;
#pragma unroll
        for (int fn = 0; fn < 4; fn++) {
            int col = colbase + wn + fn * 8 + 2 * tg;
            if constexpr (MODE == 1) {
                // wsrc = bias
                float2 bb = *reinterpret_cast<const float2*>(wsrc + col);
                float2 v0 = make_float2(acc[fm][fn][0] + bb.x, acc[fm][fn][1] + bb.y);
                float2 v1 = make_float2(acc[fm][fn][2] + bb.x, acc[fm][fn][3] + bb.y);
                *reinterpret_cast<float2*>(&Cout[(size_t)r0 * NOUT + col]) = v0;
                *reinterpret_cast<float2*>(&Cout[(size_t)(r0 + 8) * NOUT + col]) = v1;
            } else {
                // wsrc = qkv_w (f32); add delta in f32, round once to fp16
                int e0 = (blockIdx.z ? 2 * DD : 0) + r0;
                float2 w0 = *reinterpret_cast<const float2*>(&wsrc[(size_t)e0 * DD + col]);
                float2 w1 = *reinterpret_cast<const float2*>(&wsrc[(size_t)(e0 + 8) * DD + col]);
                __half2 h0 = __floats2half2_rn(acc[fm][fn][0] + w0.x, acc[fm][fn][1] + w0.y);
                __half2 h1 = __floats2half2_rn(acc[fm][fn][2] + w1.x, acc[fm][fn][3] + w1.y);
                *reinterpret_cast<__half2*>(&g_wt[(size_t)e0 * DD + col]) = h0;
                *reinterpret_cast<__half2*>(&g_wt[(size_t)(e0 + 8) * DD + col]) = h1;
            }
        }
    }
}

// ---------------- launch ----------------
extern "C" void kernel_launch(void* const* d_in, const int* in_sizes, int n_in,
                              void* d_out, int out_size) {
    const float* x     = (const float*)d_in[0];
    const float* qkv_w = (const float*)d_in[1];
    const float* qkv_b = (const float*)d_in[2];
    const float* la_q  = (const float*)d_in[3];
    const float* lb_q  = (const float*)d_in[4];
    const float* la_v  = (const float*)d_in[5];
    const float* lb_v  = (const float*)d_in[6];
    const float* A_q   = (const float*)d_in[7];
    const float* B_q   = (const float*)d_in[8];
    const float* A_v   = (const float*)d_in[9];
    const float* B_v   = (const float*)d_in[10];
    const float* gate  = (const float*)d_in[11];
    const float* alpha = (const float*)d_in[12];

    const int SMEM = NS * (BM + BN) * LDSH * (int)sizeof(__half);  // 138240
    cudaFuncSetAttribute((const void*)gemm_fp16<0>,
                         cudaFuncAttributeMaxDynamicSharedMemorySize, SMEM);
    cudaFuncSetAttribute((const void*)gemm_fp16<1>,
                         cudaFuncAttributeMaxDynamicSharedMemorySize, SMEM);

    // Fused prepass: x convert (768 blk) | w-mid convert (72 blk) | norms (32 blk)
    prep_kernel<<<872, 256>>>((const float4*)x,
                              (const float4*)(qkv_w + (size_t)DD * DD),
                              A_q, B_q, A_v, B_v);

    build_kernel<<<144, 256>>>(A_q, la_q, A_v, la_v, B_q, lb_q, B_v, lb_v, gate, alpha);

    // Fold low-rank into weights: W' = W + B_s @ A^T  (writes g_wt q/v thirds)
    gemm_fp16<0><<<dim3(4, 6, 2), NTHR, SMEM>>>(qkv_w, nullptr);

    // Main GEMM: out = xt @ wt^T + bias  (uniform K=768)
    gemm_fp16<1><<<dim3(12, 64, 1), NTHR, SMEM>>>(qkv_b, (float*)d_out);
}

// round 15
// speedup vs baseline: 1.1823x; 1.1823x over previous
#include <cuda_runtime.h>
#include <cuda_fp16.h>
#include <cstdint>
#include <math.h>

// ---------------- problem constants ----------------
#define DD 768
#define RR 16
#define TT 8
#define M_ROWS 8192
#define NOUT 2304
#define KM2 192          // padded low-rank K per branch (144 real + 48 zero)

// ---------------- static scratch ----------------
__device__ __align__(16) __half g_xt[M_ROWS * DD];    // x in fp16
__device__ __align__(16) __half g_wt[NOUT * DD];      // W (+ folded dW) in fp16
__device__ __align__(16) __half g_Bqs[DD * KM2];      // scaled B_q  [e][j]
__device__ __align__(16) __half g_Bvs[DD * KM2];
__device__ __align__(16) __half g_AqT[DD * KM2];      // A_q^T       [d][j]
__device__ __align__(16) __half g_AvT[DD * KM2];
__device__ float g_normsq[32];                        // [Aq(8),Bq(8),Av(8),Bv(8)]

// ---------------- helpers ----------------
__device__ __forceinline__ void cp16(void* sdst, const void* gsrc) {
    unsigned s = (unsigned)__cvta_generic_to_shared(sdst);
    asm volatile("cp.async.cg.shared.global [%0], [%1], 16;\n" :: "r"(s), "l"(gsrc));
}

__device__ __forceinline__ void ldm_x4(uint32_t& d0, uint32_t& d1, uint32_t& d2,
                                       uint32_t& d3, uint32_t saddr) {
    asm volatile("ldmatrix.sync.aligned.m8n8.x4.shared.b16 {%0,%1,%2,%3}, [%4];"
                 : "=r"(d0), "=r"(d1), "=r"(d2), "=r"(d3) : "r"(saddr));
}

__device__ __forceinline__ void mma_fp16(float c[4], const uint32_t a[4], const uint32_t b[2]) {
    asm volatile(
        "mma.sync.aligned.m16n8k16.row.col.f32.f16.f16.f32 "
        "{%0,%1,%2,%3},{%4,%5,%6,%7},{%8,%9},{%0,%1,%2,%3};\n"
        : "+f"(c[0]), "+f"(c[1]), "+f"(c[2]), "+f"(c[3])
        : "r"(a[0]), "r"(a[1]), "r"(a[2]), "r"(a[3]),
          "r"(b[0]), "r"(b[1]));
}

// ---------------- fused prepass: x-convert | w-convert | norms ----------------
__device__ __forceinline__ void convert_seg(const float4* __restrict__ src,
                                            uint4* __restrict__ dst,
                                            int bid_local, int nb) {
    const int stride = nb * 256;
    int i = bid_local * 256 + threadIdx.x;
#pragma unroll
    for (int u = 0; u < 4; u++) {
        int k = i + u * stride;
        float4 a = src[2 * k], b = src[2 * k + 1];
        __half2 h0 = __floats2half2_rn(a.x, a.y);
        __half2 h1 = __floats2half2_rn(a.z, a.w);
        __half2 h2 = __floats2half2_rn(b.x, b.y);
        __half2 h3 = __floats2half2_rn(b.z, b.w);
        uint4 o;
        o.x = *reinterpret_cast<uint32_t*>(&h0);
        o.y = *reinterpret_cast<uint32_t*>(&h1);
        o.z = *reinterpret_cast<uint32_t*>(&h2);
        o.w = *reinterpret_cast<uint32_t*>(&h3);
        dst[k] = o;
    }
}

__global__ void prep_kernel(const float4* __restrict__ x, const float4* __restrict__ wmid,
                            const float* __restrict__ Aq, const float* __restrict__ Bq,
                            const float* __restrict__ Av, const float* __restrict__ Bv) {
    int bid = blockIdx.x;
    if (bid < 768) {
        convert_seg(x, (uint4*)g_xt, bid, 768);
    } else if (bid < 840) {
        convert_seg(wmid, (uint4*)(g_wt + (size_t)DD * DD), bid - 768, 72);
    } else {
        __shared__ float red[256];
        int b = bid - 840, which = b >> 3, t = b & 7;
        const float* p = (which == 0) ? Aq : (which == 1) ? Bq : (which == 2) ? Av : Bv;
        p += t * (RR * DD);
        float s = 0.f;
        for (int i = threadIdx.x; i < RR * DD; i += 256) { float v = p[i]; s += v * v; }
        red[threadIdx.x] = s;
        __syncthreads();
        for (int o = 128; o > 0; o >>= 1) {
            if (threadIdx.x < o) red[threadIdx.x] += red[threadIdx.x + o];
            __syncthreads();
        }
        if (threadIdx.x == 0) g_normsq[b] = red[0];
    }
}

// Builds (fp16): Bqs/Bvs [768][192] with beta/norm (or alpha) folded in,
// and AqT/AvT [768][192] = transposed A stacks. Cols 144-191 zero.
__global__ void build_kernel(const float* __restrict__ Aq, const float* __restrict__ laq,
                             const float* __restrict__ Av, const float* __restrict__ lav,
                             const float* __restrict__ Bq, const float* __restrict__ lbq,
                             const float* __restrict__ Bv, const float* __restrict__ lbv,
                             const float* __restrict__ gate, const float* __restrict__ alpha) {
    float sq[TT], sv[TT];
    {
        float mx = gate[0];
        for (int t = 1; t < TT; t++) mx = fmaxf(mx, gate[t]);
        float e[TT], se = 0.f;
        for (int t = 0; t < TT; t++) { e[t] = expf(gate[t] - mx); se += e[t]; }
        for (int t = 0; t < TT; t++) {
            float beta = e[t] / se;
            sq[t] = beta / (sqrtf(g_normsq[t]) * sqrtf(g_normsq[8 + t]));
            sv[t] = beta / (sqrtf(g_normsq[16 + t]) * sqrtf(g_normsq[24 + t]));
        }
    }
    float acur = alpha[TT];
    int i0 = blockIdx.x * blockDim.x + threadIdx.x;
    int stride = gridDim.x * blockDim.x;
    for (int i = i0; i < DD * KM2; i += stride) {
        int d = i / KM2, j = i % KM2;
        float bq = 0.f, bv = 0.f, aq = 0.f, av = 0.f;
        if (j < 128) {
            int t = j >> 4, r = j & 15;
            bq = Bq[t * (DD * RR) + d * RR + r] * sq[t];
            bv = Bv[t * (DD * RR) + d * RR + r] * sv[t];
            aq = Aq[j * DD + d];
            av = Av[j * DD + d];
        } else if (j < 144) {
            bq = lbq[d * RR + (j - 128)] * acur;
            bv = lbv[d * RR + (j - 128)] * acur;
            aq = laq[(j - 128) * DD + d];
            av = lav[(j - 128) * DD + d];
        }
        g_Bqs[i] = __float2half_rn(bq);
        g_Bvs[i] = __float2half_rn(bv);
        g_AqT[i] = __float2half_rn(aq);
        g_AvT[i] = __float2half_rn(av);
    }
}

// ---------------- fp16 mma.sync GEMM machinery ----------------
// Block 128x128, 4 warps in 2x2 grid, warp tile 64x64. 128 thr/CTA -> reg cap 256:
// double-buffered fragments + 2 CTAs/SM (cross-CTA barrier overlap) + halved
// LDSM redundancy (2x for both A and B) -> smem crossbar now has 25% slack.
#define NS 3
#define BM 128
#define BN 128
#define BK 64
#define NTHR 128
#define LDSH 72   // padded row (144 B): 16B-step row offsets -> conflict-free ldmatrix

// MODE 0 (delta): W'[e,d] = fp16( qkv_w[e_glob,d] + sum_j Bs[e,j]*AT[d,j] ), KT=3
//   grid (6,6,2): z=0 -> q branch (e_glob=e), z=1 -> v branch (e_glob=1536+e)
// MODE 1 (main): out[8192,2304] = xt @ wt^T + bias, KT=12, grid (18,64)
template <int MODE>
__global__ __launch_bounds__(NTHR, 2) void gemm_fp16(const float* __restrict__ wsrc,
                                                     float* __restrict__ Cout) {
    extern __shared__ __half sm[];
    __half* As = sm;                        // [NS][BM][LDSH]
    __half* Bs = sm + NS * BM * LDSH;       // [NS][BN][LDSH]

    const int tid = threadIdx.x, lane = tid & 31, w = tid >> 5;
    const int g = lane >> 2, tg = lane & 3;
    const int wm = (w >> 1) * 64, wn = (w & 1) * 64;   // 2x2 warp grid, 64x64 tiles
    const int rowbase = blockIdx.y * BM, colbase = blockIdx.x * BN;

    const __half* Ap;
    const __half* Bp;
    int ld, KT;
    if constexpr (MODE == 0) {
        const __half* Asrc = blockIdx.z ? g_Bvs : g_Bqs;
        const __half* Bsrc = blockIdx.z ? g_AvT : g_AqT;
        Ap = Asrc + (size_t)rowbase * KM2;
        Bp = Bsrc + (size_t)colbase * KM2;
        ld = KM2; KT = KM2 / BK;          // 3
    } else {
        Ap = g_xt + (size_t)rowbase * DD;
        Bp = g_wt + (size_t)colbase * DD;
        ld = DD; KT = DD / BK;            // 12
    }

    float acc[4][8][4];
#pragma unroll
    for (int i = 0; i < 4; i++)
#pragma unroll
        for (int j = 0; j < 8; j++)
#pragma unroll
            for (int k = 0; k < 4; k++) acc[i][j][k] = 0.f;

    auto load_tile = [&](int stg, int kt) {
        int kc = kt * BK;
        __half* Ad = As + stg * (BM * LDSH);
        __half* Bd = Bs + stg * (BN * LDSH);
#pragma unroll
        for (int i = 0; i < 8; i++) {   // A: 128 rows x 8 chunks = 1024, 128 thr
            int v = tid + i * NTHR, r = v >> 3, c = (v & 7) << 3;
            cp16(Ad + r * LDSH + c, Ap + (size_t)r * ld + kc + c);
        }
#pragma unroll
        for (int i = 0; i < 8; i++) {   // B: same shape
            int v = tid + i * NTHR, r = v >> 3, c = (v & 7) << 3;
            cp16(Bd + r * LDSH + c, Bp + (size_t)r * ld + kc + c);
        }
    };

    load_tile(0, 0);
    asm volatile("cp.async.commit_group;\n" ::);
    load_tile(1, 1);
    asm volatile("cp.async.commit_group;\n" ::);

    const uint32_t a_base = (uint32_t)__cvta_generic_to_shared(As);
    const uint32_t b_base = (uint32_t)__cvta_generic_to_shared(Bs);
    const int a_row = wm + (lane & 15);
    const int a_csel = (lane >> 4) << 3;
    const int b_row = wn + (lane & 7) + ((lane >> 4) << 3);
    const int b_csel = ((lane >> 3) & 1) << 3;

    // double-buffered fragments (ks-pipelined)
    uint32_t afr[2][4][4], bfr[2][8][2];

    auto load_frags = [&](int stg, int ks, int buf) {
        const int kk = ks * 16;
#pragma unroll
        for (int fm = 0; fm < 4; fm++) {
            uint32_t addr = a_base +
                (uint32_t)(((stg * BM) + a_row + fm * 16) * LDSH + kk + a_csel) * 2;
            ldm_x4(afr[buf][fm][0], afr[buf][fm][1], afr[buf][fm][2], afr[buf][fm][3], addr);
        }
#pragma unroll
        for (int fn2 = 0; fn2 < 4; fn2++) {
            uint32_t addr = b_base +
                (uint32_t)(((stg * BN) + b_row + fn2 * 16) * LDSH + kk + b_csel) * 2;
            uint32_t r0, r1, r2, r3;
            ldm_x4(r0, r1, r2, r3, addr);
            bfr[buf][fn2 * 2][0] = r0;     bfr[buf][fn2 * 2][1] = r1;
            bfr[buf][fn2 * 2 + 1][0] = r2; bfr[buf][fn2 * 2 + 1][1] = r3;
        }
    };

    for (int kt = 0; kt < KT; kt++) {
        const int stg = kt % NS;
        if (kt == KT - 1) asm volatile("cp.async.wait_group 0;\n" ::);
        else              asm volatile("cp.async.wait_group 1;\n" ::);
        __syncthreads();
        if (kt + 2 < KT) {
            load_tile((kt + 2) % NS, kt + 2);
            asm volatile("cp.async.commit_group;\n" ::);
        }
        load_frags(stg, 0, 0);
#pragma unroll
        for (int ks = 0; ks < 4; ks++) {
            const int cur = ks & 1;
            if (ks < 3) load_frags(stg, ks + 1, cur ^ 1);
#pragma unroll
            for (int fm = 0; fm < 4; fm++)
#pragma unroll
                for (int fn = 0; fn < 8; fn++)
                    mma_fp16(acc[fm][fn], afr[cur][fm], bfr[cur][fn]);
        }
    }

    // epilogue
#pragma unroll
    for (int fm = 0; fm < 4; fm++) {
        int r0 = rowbase + wm + fm * 16 + g;
#pragma unroll
        for (int fn = 0; fn < 8; fn++) {
            int col = colbase + wn + fn * 8 + 2 * tg;
            if constexpr (MODE == 1) {
                // wsrc = bias
                float2 bb = *reinterpret_cast<const float2*>(wsrc + col);
                float2 v0 = make_float2(acc[fm][fn][0] + bb.x, acc[fm][fn][1] + bb.y);
                float2 v1 = make_float2(acc[fm][fn][2] + bb.x, acc[fm][fn][3] + bb.y);
                *reinterpret_cast<float2*>(&Cout[(size_t)r0 * NOUT + col]) = v0;
                *reinterpret_cast<float2*>(&Cout[(size_t)(r0 + 8) * NOUT + col]) = v1;
            } else {
                // wsrc = qkv_w (f32); add delta in f32, round once to fp16
                int e0 = (blockIdx.z ? 2 * DD : 0) + r0;
                float2 w0 = *reinterpret_cast<const float2*>(&wsrc[(size_t)e0 * DD + col]);
                float2 w1 = *reinterpret_cast<const float2*>(&wsrc[(size_t)(e0 + 8) * DD + col]);
                __half2 h0 = __floats2half2_rn(acc[fm][fn][0] + w0.x, acc[fm][fn][1] + w0.y);
                __half2 h1 = __floats2half2_rn(acc[fm][fn][2] + w1.x, acc[fm][fn][3] + w1.y);
                *reinterpret_cast<__half2*>(&g_wt[(size_t)e0 * DD + col]) = h0;
                *reinterpret_cast<__half2*>(&g_wt[(size_t)(e0 + 8) * DD + col]) = h1;
            }
        }
    }
}

// ---------------- launch ----------------
extern "C" void kernel_launch(void* const* d_in, const int* in_sizes, int n_in,
                              void* d_out, int out_size) {
    const float* x     = (const float*)d_in[0];
    const float* qkv_w = (const float*)d_in[1];
    const float* qkv_b = (const float*)d_in[2];
    const float* la_q  = (const float*)d_in[3];
    const float* lb_q  = (const float*)d_in[4];
    const float* la_v  = (const float*)d_in[5];
    const float* lb_v  = (const float*)d_in[6];
    const float* A_q   = (const float*)d_in[7];
    const float* B_q   = (const float*)d_in[8];
    const float* A_v   = (const float*)d_in[9];
    const float* B_v   = (const float*)d_in[10];
    const float* gate  = (const float*)d_in[11];
    const float* alpha = (const float*)d_in[12];

    const int SMEM = NS * (BM + BN) * LDSH * (int)sizeof(__half);  // 110592
    cudaFuncSetAttribute((const void*)gemm_fp16<0>,
                         cudaFuncAttributeMaxDynamicSharedMemorySize, SMEM);
    cudaFuncSetAttribute((const void*)gemm_fp16<1>,
                         cudaFuncAttributeMaxDynamicSharedMemorySize, SMEM);

    // Fused prepass: x convert (768 blk) | w-mid convert (72 blk) | norms (32 blk)
    prep_kernel<<<872, 256>>>((const float4*)x,
                              (const float4*)(qkv_w + (size_t)DD * DD),
                              A_q, B_q, A_v, B_v);

    build_kernel<<<144, 256>>>(A_q, la_q, A_v, la_v, B_q, lb_q, B_v, lb_v, gate, alpha);

    // Fold low-rank into weights: W' = W + B_s @ A^T  (writes g_wt q/v thirds)
    gemm_fp16<0><<<dim3(6, 6, 2), NTHR, SMEM>>>(qkv_w, nullptr);

    // Main GEMM: out = xt @ wt^T + bias  (uniform K=768)
    gemm_fp16<1><<<dim3(18, 64, 1), NTHR, SMEM>>>(qkv_b, (float*)d_out);
}